// round 1
// baseline (speedup 1.0000x reference)
#include <cuda_runtime.h>
#include <math.h>

#define CIN   64
#define COUT  64
#define HH    112
#define WW    112
#define NB    32
#define HW    (HH*WW)            // 12544
#define TOTAL (NB*COUT*HW)       // 25690112
#define MCNT  (NB*HW)            // 401408

// ---------------- device scratch (allocation-free) ----------------
__device__ float g_t1[TOTAL];            // conv1 raw output
__device__ float g_t2[TOTAL];            // conv2 + residual (pre-BN2)
__device__ float g_w1[CIN*COUT*9];       // ternarized, [ci][co][k]
__device__ float g_w2[CIN*COUT*9];
__device__ float g_sum[2][COUT];
__device__ float g_sq[2][COUT];
__device__ float g_scale[2][COUT];
__device__ float g_bias[2][COUT];

// ---------------- prep: ternarize + repack + zero stats ----------------
__global__ void prep_kernel(const float* __restrict__ w1,
                            const float* __restrict__ w2) {
    int idx = blockIdx.x * 256 + threadIdx.x;
    if (idx < COUT) {
        g_sum[0][idx] = 0.f; g_sum[1][idx] = 0.f;
        g_sq[0][idx]  = 0.f; g_sq[1][idx]  = 0.f;
    }
    if (idx < CIN*COUT*9) {
        // source layout OIHW: idx = (co*CIN + ci)*9 + k
        int co = idx / (CIN*9);
        int ci = (idx / 9) % CIN;
        int k  = idx % 9;
        int dst = (ci*COUT + co)*9 + k;
        float a = w1[idx];
        g_w1[dst] = (fabsf(a) > 0.3f) ? (a > 0.f ? 1.f : -1.f) : 0.f;
        float b = w2[idx];
        g_w2[dst] = (fabsf(b) > 0.3f) ? (b > 0.f ? 1.f : -1.f) : 0.f;
    }
}

// ---------------- conv3x3 (pad 1), 16x16 pixel tile per block ----------------
// PASS==1: in = x, out = g_t1 (raw conv)
// PASS==2: in = g_t1 with fused BN1+hardtanh applied on load (padding zeros
//          applied AFTER activation, matching the reference), out = g_t2 with
//          residual x added in the epilogue.
template<int PASS>
__global__ void __launch_bounds__(256, 2) conv_kernel(const float* __restrict__ x) {
    const float* in   = (PASS == 1) ? x    : g_t1;
    const float* wrep = (PASS == 1) ? g_w1 : g_w2;
    float*       out  = (PASS == 1) ? g_t1 : g_t2;

    __shared__ float s_in[18*18];
    __shared__ float s_w[COUT*9];
    __shared__ float s_s[COUT];
    __shared__ float s_b[COUT];

    const int tid = threadIdx.x;
    const int tx = tid & 15;
    const int ty = tid >> 4;
    const int w0 = blockIdx.x * 16;
    const int h0 = blockIdx.y * 16;
    const int n  = blockIdx.z;

    if (PASS == 2 && tid < COUT) {
        s_s[tid] = g_scale[0][tid];
        s_b[tid] = g_bias[0][tid];
    }

    float acc[COUT];
#pragma unroll
    for (int i = 0; i < COUT; i++) acc[i] = 0.f;

    for (int ci = 0; ci < CIN; ++ci) {
        __syncthreads();   // protect smem reuse (and s_s/s_b init on iter 0)

        // stage this ci's 64*9 ternary weights
        for (int i = tid; i < COUT*9; i += 256)
            s_w[i] = wrep[ci*(COUT*9) + i];

        // stage 18x18 input tile (with halo)
        const float* ip = in + (n*CIN + ci) * HW;
        float sc = 0.f, bs = 0.f;
        if (PASS == 2) { sc = s_s[ci]; bs = s_b[ci]; }
        for (int i = tid; i < 18*18; i += 256) {
            int r  = i / 18;
            int c  = i - r*18;
            int gh = h0 + r - 1;
            int gw = w0 + c - 1;
            float v = 0.f;
            if ((unsigned)gh < (unsigned)HH && (unsigned)gw < (unsigned)WW) {
                v = ip[gh*WW + gw];
                if (PASS == 2)
                    v = fminf(fmaxf(fmaf(v, sc, bs), -1.f), 1.f);
            }
            s_in[i] = v;
        }
        __syncthreads();

        float v[9];
#pragma unroll
        for (int dy = 0; dy < 3; dy++)
#pragma unroll
            for (int dx = 0; dx < 3; dx++)
                v[dy*3 + dx] = s_in[(ty + dy)*18 + (tx + dx)];

#pragma unroll
        for (int co = 0; co < COUT; ++co) {
            float a = acc[co];
#pragma unroll
            for (int k = 0; k < 9; k++)
                a = fmaf(s_w[co*9 + k], v[k], a);
            acc[co] = a;
        }
    }

    const int h = h0 + ty;
    const int w = w0 + tx;
    const int base = n*COUT*HW + h*WW + w;
#pragma unroll
    for (int co = 0; co < COUT; ++co) {
        float val = acc[co];
        if (PASS == 2) val += x[base + co*HW];   // residual
        out[base + co*HW] = val;
    }
}

// ---------------- per-channel batch stats (sum, sumsq) ----------------
template<int PASS>
__global__ void stats_kernel() {
    const float* t = (PASS == 1) ? g_t1 : g_t2;
    const int c = blockIdx.x & 63;
    const int n = blockIdx.x >> 6;
    const float* p = t + (n*COUT + c) * HW;

    float s = 0.f, q = 0.f;
    for (int i = threadIdx.x; i < HW; i += 256) {
        float v = p[i];
        s += v;
        q = fmaf(v, v, q);
    }
#pragma unroll
    for (int o = 16; o; o >>= 1) {
        s += __shfl_down_sync(0xffffffffu, s, o);
        q += __shfl_down_sync(0xffffffffu, q, o);
    }
    __shared__ float ss[8], sq[8];
    const int wid = threadIdx.x >> 5;
    if ((threadIdx.x & 31) == 0) { ss[wid] = s; sq[wid] = q; }
    __syncthreads();
    if (threadIdx.x == 0) {
        float S = 0.f, Q = 0.f;
#pragma unroll
        for (int i = 0; i < 8; i++) { S += ss[i]; Q += sq[i]; }
        atomicAdd(&g_sum[PASS-1][c], S);
        atomicAdd(&g_sq[PASS-1][c], Q);
    }
}

// ---------------- fold BN stats into scale/bias ----------------
template<int PASS>
__global__ void finalize_kernel(const float* __restrict__ g,
                                const float* __restrict__ b) {
    int c = threadIdx.x;
    if (c < COUT) {
        const float inv = 1.f / (float)MCNT;
        float mean = g_sum[PASS-1][c] * inv;
        float var  = g_sq[PASS-1][c] * inv - mean*mean;
        float s    = g[c] * rsqrtf(var + 1e-5f);
        g_scale[PASS-1][c] = s;
        g_bias[PASS-1][c]  = b[c] - mean*s;
    }
}

// ---------------- final BN2 + hardtanh -> d_out (float4) ----------------
__global__ void bnact_kernel(float* __restrict__ out) {
    int i = blockIdx.x * 256 + threadIdx.x;      // float4 index
    if (i >= TOTAL/4) return;
    int c = (i / (HW/4)) & 63;                   // HW % 4 == 0
    float s  = g_scale[1][c];
    float bb = g_bias[1][c];
    float4 v = reinterpret_cast<const float4*>(g_t2)[i];
    v.x = fminf(fmaxf(fmaf(v.x, s, bb), -1.f), 1.f);
    v.y = fminf(fmaxf(fmaf(v.y, s, bb), -1.f), 1.f);
    v.z = fminf(fmaxf(fmaf(v.z, s, bb), -1.f), 1.f);
    v.w = fminf(fmaxf(fmaf(v.w, s, bb), -1.f), 1.f);
    reinterpret_cast<float4*>(out)[i] = v;
}

// ---------------- launch ----------------
extern "C" void kernel_launch(void* const* d_in, const int* in_sizes, int n_in,
                              void* d_out, int out_size) {
    const float* x  = (const float*)d_in[0];
    const float* w1 = (const float*)d_in[1];
    const float* g1 = (const float*)d_in[2];
    const float* b1 = (const float*)d_in[3];
    const float* w2 = (const float*)d_in[4];
    const float* g2 = (const float*)d_in[5];
    const float* b2 = (const float*)d_in[6];
    float* out = (float*)d_out;

    prep_kernel<<<(CIN*COUT*9 + 255)/256, 256>>>(w1, w2);

    dim3 cgrid(WW/16, HH/16, NB);   // (7, 7, 32)
    conv_kernel<1><<<cgrid, 256>>>(x);
    stats_kernel<1><<<NB*COUT, 256>>>();
    finalize_kernel<1><<<1, 64>>>(g1, b1);

    conv_kernel<2><<<cgrid, 256>>>(x);
    stats_kernel<2><<<NB*COUT, 256>>>();
    finalize_kernel<2><<<1, 64>>>(g2, b2);

    bnact_kernel<<<(TOTAL/4 + 255)/256, 256>>>(out);
}

// round 3
// speedup vs baseline: 3.1951x; 3.1951x over previous
#include <cuda_runtime.h>
#include <math.h>
#include <stdint.h>

#define CIN   64
#define COUT  64
#define HH    112
#define WW    112
#define NB    32
#define HW    (HH*WW)            // 12544
#define TOTAL (NB*COUT*HW)       // 25690112
#define MCNT  (NB*HW)            // 401408

// conv tiling
#define TPX 16
#define TPY 8
#define ACT_STRIDE 68
#define W_STRIDE   68
#define S_ACT_SIZE (10*18*ACT_STRIDE)        // 12240 floats
#define S_W_SIZE   (64*W_STRIDE)             // 4352 floats
#define SMEM_BYTES ((S_ACT_SIZE + S_W_SIZE)*4)

// ---------------- device scratch ----------------
__device__ float g_t1[TOTAL];
__device__ float g_t2[TOTAL];
__device__ float g_w1[9*COUT*64];   // [tap][co][ci_interleaved]
__device__ float g_w2[9*COUT*64];
__device__ float g_sum[2][COUT];
__device__ float g_sq[2][COUT];
__device__ float g_scale[2][COUT];
__device__ float g_bias[2][COUT];

__device__ __forceinline__ uint32_t to_tf32_bits(float x) {
    uint32_t r;
    asm("cvt.rna.tf32.f32 %0, %1;" : "=r"(r) : "f"(x));
    return r;
}
__device__ __forceinline__ uint32_t fau(float x) { return __float_as_uint(x); }

__device__ __forceinline__ void mma8(float* d, const uint32_t* a, uint32_t b0, uint32_t b1) {
    asm volatile(
        "mma.sync.aligned.m16n8k8.row.col.f32.tf32.tf32.f32 "
        "{%0,%1,%2,%3}, {%4,%5,%6,%7}, {%8,%9}, {%0,%1,%2,%3};\n"
        : "+f"(d[0]), "+f"(d[1]), "+f"(d[2]), "+f"(d[3])
        : "r"(a[0]), "r"(a[1]), "r"(a[2]), "r"(a[3]), "r"(b0), "r"(b1));
}

// interleave within each 8-group: [0,4,1,5,2,6,3,7] -> fragment pairs are v2-adjacent
__device__ __forceinline__ int ci_slot(int ci) {
    int grp = ci >> 3, q = ci & 3, hi = (ci >> 2) & 1;
    return grp*8 + q*2 + hi;
}

// ---------------- prep: ternarize + repack + zero stats ----------------
__global__ void prep_kernel(const float* __restrict__ w1,
                            const float* __restrict__ w2) {
    int idx = blockIdx.x * 256 + threadIdx.x;
    if (idx < COUT) {
        g_sum[0][idx] = 0.f; g_sum[1][idx] = 0.f;
        g_sq[0][idx]  = 0.f; g_sq[1][idx]  = 0.f;
    }
    if (idx < 9*COUT*64) {
        // src OIHW: idx = (co*64 + ci)*9 + t
        int co = idx / (64*9);
        int ci = (idx / 9) & 63;
        int t  = idx % 9;
        int dst = t*4096 + co*64 + ci_slot(ci);
        float a = w1[idx];
        g_w1[dst] = (fabsf(a) > 0.3f) ? (a > 0.f ? 1.f : -1.f) : 0.f;
        float b = w2[idx];
        g_w2[dst] = (fabsf(b) > 0.3f) ? (b > 0.f ? 1.f : -1.f) : 0.f;
    }
}

// ---------------- conv3x3 via 9 shifted 1x1 GEMMs, tf32 mma ----------------
// PASS 1: in=x (raw), out=g_t1
// PASS 2: in=g_t1 with BN1+hardtanh fused on smem load, out=g_t2 (+residual x)
template<int PASS>
__global__ void __launch_bounds__(256, 2) conv_mma_kernel(const float* __restrict__ x) {
    extern __shared__ float smem[];
    float* s_act = smem;                 // [py][px][ci'] stride ACT_STRIDE
    float* s_w   = smem + S_ACT_SIZE;    // [co][k'] stride W_STRIDE
    __shared__ float s_s[COUT], s_b[COUT];

    const float* in   = (PASS == 1) ? x    : g_t1;
    const float* wrep = (PASS == 1) ? g_w1 : g_w2;
    float*       out  = (PASS == 1) ? g_t1 : g_t2;

    const int tid  = threadIdx.x;
    const int lane = tid & 31;
    const int wid  = tid >> 5;
    const int wm   = wid & 1;        // 2 m-tiles of 32
    const int wn   = wid >> 1;       // 4 n-tiles of 32
    const int q    = lane & 3;
    const int nidx = lane >> 2;
    const int w0   = blockIdx.x * TPX;
    const int h0   = blockIdx.y * TPY;
    const int n    = blockIdx.z;

    if (PASS == 2 && tid < COUT) {
        s_s[tid] = g_scale[0][tid];
        s_b[tid] = g_bias[0][tid];
    }
    __syncthreads();

    // stage activation tile: 64 ci x 10 x 18 (halo), tf32-rounded
    for (int i = tid; i < 64*180; i += 256) {
        int ci  = i / 180;
        int rem = i - ci*180;
        int py  = rem / 18;
        int px  = rem - py*18;
        int gh = h0 + py - 1, gw = w0 + px - 1;
        float v = 0.f;
        if ((unsigned)gh < (unsigned)HH && (unsigned)gw < (unsigned)WW) {
            v = in[(n*64 + ci)*HW + gh*WW + gw];
            if (PASS == 2)
                v = fminf(fmaxf(fmaf(v, s_s[ci], s_b[ci]), -1.f), 1.f);
        }
        s_act[(py*18 + px)*ACT_STRIDE + ci_slot(ci)] = __uint_as_float(to_tf32_bits(v));
    }

    float acc[2][4][4];
#pragma unroll
    for (int mt = 0; mt < 2; mt++)
#pragma unroll
        for (int nt = 0; nt < 4; nt++)
#pragma unroll
            for (int r = 0; r < 4; r++) acc[mt][nt][r] = 0.f;

    for (int tap = 0; tap < 9; ++tap) {
        __syncthreads();   // previous tap's reads done before s_w overwrite
        const float* wsrc = wrep + tap*4096;
        for (int i = tid; i < 4096; i += 256)
            s_w[(i >> 6)*W_STRIDE + (i & 63)] = wsrc[i];
        __syncthreads();

        const int dy = tap / 3, dx = tap - dy*3;

        unsigned baddr[4];
#pragma unroll
        for (int nt = 0; nt < 4; nt++) {
            int p  = wn*32 + nt*8 + nidx;
            int py = p >> 4, px = p & 15;
            baddr[nt] = ((py + dy)*18 + (px + dx))*ACT_STRIDE + 2*q;
        }
        unsigned aaddr[2][2];
#pragma unroll
        for (int mt = 0; mt < 2; mt++) {
            int r0 = wm*32 + mt*16 + nidx;
            aaddr[mt][0] = r0*W_STRIDE + 2*q;
            aaddr[mt][1] = (r0 + 8)*W_STRIDE + 2*q;
        }

#pragma unroll
        for (int kc = 0; kc < 8; kc++) {
            const int ko = kc*8;
            uint32_t a[2][4];
#pragma unroll
            for (int mt = 0; mt < 2; mt++) {
                float2 a02 = *(const float2*)(s_w + aaddr[mt][0] + ko);
                float2 a13 = *(const float2*)(s_w + aaddr[mt][1] + ko);
                a[mt][0] = fau(a02.x); a[mt][1] = fau(a13.x);
                a[mt][2] = fau(a02.y); a[mt][3] = fau(a13.y);
            }
#pragma unroll
            for (int nt = 0; nt < 4; nt++) {
                float2 b01 = *(const float2*)(s_act + baddr[nt] + ko);
                uint32_t b0 = fau(b01.x), b1 = fau(b01.y);
#pragma unroll
                for (int mt = 0; mt < 2; mt++)
                    mma8(acc[mt][nt], a[mt], b0, b1);
            }
        }
    }

    // epilogue: D frag -> NCHW (float2 stores), PASS2 adds residual
#pragma unroll
    for (int mt = 0; mt < 2; mt++) {
        int co0 = wm*32 + mt*16 + nidx;
#pragma unroll
        for (int nt = 0; nt < 4; nt++) {
            int p  = wn*32 + nt*8 + 2*q;
            int py = p >> 4, px = p & 15;
            int base = (n*64 + co0)*HW + (h0 + py)*WW + (w0 + px);
            float2 v0 = make_float2(acc[mt][nt][0], acc[mt][nt][1]);
            float2 v1 = make_float2(acc[mt][nt][2], acc[mt][nt][3]);
            if (PASS == 2) {
                float2 r0 = *(const float2*)(x + base);
                float2 r1 = *(const float2*)(x + base + 8*HW);
                v0.x += r0.x; v0.y += r0.y;
                v1.x += r1.x; v1.y += r1.y;
            }
            *(float2*)(out + base)        = v0;
            *(float2*)(out + base + 8*HW) = v1;
        }
    }
}

// ---------------- per-channel batch stats ----------------
template<int PASS>
__global__ void stats_kernel() {
    const float* t = (PASS == 1) ? g_t1 : g_t2;
    const int c = blockIdx.x & 63;
    const int n = blockIdx.x >> 6;
    const float* p = t + (n*COUT + c) * HW;

    float s = 0.f, qq = 0.f;
    for (int i = threadIdx.x; i < HW; i += 256) {
        float v = p[i];
        s += v;
        qq = fmaf(v, v, qq);
    }
#pragma unroll
    for (int o = 16; o; o >>= 1) {
        s  += __shfl_down_sync(0xffffffffu, s, o);
        qq += __shfl_down_sync(0xffffffffu, qq, o);
    }
    __shared__ float ss[8], sq[8];
    const int wwid = threadIdx.x >> 5;
    if ((threadIdx.x & 31) == 0) { ss[wwid] = s; sq[wwid] = qq; }
    __syncthreads();
    if (threadIdx.x == 0) {
        float S = 0.f, Q = 0.f;
#pragma unroll
        for (int i = 0; i < 8; i++) { S += ss[i]; Q += sq[i]; }
        atomicAdd(&g_sum[PASS-1][c], S);
        atomicAdd(&g_sq[PASS-1][c], Q);
    }
}

// ---------------- fold BN stats ----------------
template<int PASS>
__global__ void finalize_kernel(const float* __restrict__ g,
                                const float* __restrict__ b) {
    int c = threadIdx.x;
    if (c < COUT) {
        const float inv = 1.f / (float)MCNT;
        float mean = g_sum[PASS-1][c] * inv;
        float var  = g_sq[PASS-1][c] * inv - mean*mean;
        float s    = g[c] * rsqrtf(var + 1e-5f);
        g_scale[PASS-1][c] = s;
        g_bias[PASS-1][c]  = b[c] - mean*s;
    }
}

// ---------------- final BN2 + hardtanh ----------------
__global__ void bnact_kernel(float* __restrict__ out) {
    int i = blockIdx.x * 256 + threadIdx.x;
    if (i >= TOTAL/4) return;
    int c = (i / (HW/4)) & 63;
    float s  = g_scale[1][c];
    float bb = g_bias[1][c];
    float4 v = reinterpret_cast<const float4*>(g_t2)[i];
    v.x = fminf(fmaxf(fmaf(v.x, s, bb), -1.f), 1.f);
    v.y = fminf(fmaxf(fmaf(v.y, s, bb), -1.f), 1.f);
    v.z = fminf(fmaxf(fmaf(v.z, s, bb), -1.f), 1.f);
    v.w = fminf(fmaxf(fmaf(v.w, s, bb), -1.f), 1.f);
    reinterpret_cast<float4*>(out)[i] = v;
}

// ---------------- launch ----------------
extern "C" void kernel_launch(void* const* d_in, const int* in_sizes, int n_in,
                              void* d_out, int out_size) {
    const float* x  = (const float*)d_in[0];
    const float* w1 = (const float*)d_in[1];
    const float* g1 = (const float*)d_in[2];
    const float* b1 = (const float*)d_in[3];
    const float* w2 = (const float*)d_in[4];
    const float* g2 = (const float*)d_in[5];
    const float* b2 = (const float*)d_in[6];
    float* out = (float*)d_out;

    cudaFuncSetAttribute(conv_mma_kernel<1>,
                         cudaFuncAttributeMaxDynamicSharedMemorySize, SMEM_BYTES);
    cudaFuncSetAttribute(conv_mma_kernel<2>,
                         cudaFuncAttributeMaxDynamicSharedMemorySize, SMEM_BYTES);

    prep_kernel<<<(9*COUT*64 + 255)/256, 256>>>(w1, w2);

    dim3 cgrid(WW/TPX, HH/TPY, NB);   // (7, 14, 32)
    conv_mma_kernel<1><<<cgrid, 256, SMEM_BYTES>>>(x);
    stats_kernel<1><<<NB*COUT, 256>>>();
    finalize_kernel<1><<<1, 64>>>(g1, b1);

    conv_mma_kernel<2><<<cgrid, 256, SMEM_BYTES>>>(x);
    stats_kernel<2><<<NB*COUT, 256>>>();
    finalize_kernel<2><<<1, 64>>>(g2, b2);

    bnact_kernel<<<(TOTAL/4 + 255)/256, 256>>>(out);
}

// round 4
// speedup vs baseline: 4.0364x; 1.2633x over previous
#include <cuda_runtime.h>
#include <math.h>
#include <stdint.h>

#define CIN   64
#define COUT  64
#define HH    112
#define WW    112
#define NB    32
#define HW    (HH*WW)            // 12544
#define TOTAL (NB*COUT*HW)       // 25690112
#define MCNT  (NB*HW)            // 401408

// conv tiling: block = 64 co x 256 px (16x16), 8 warps m32xn64
#define TPX 16
#define TPY 16
#define NPOS (18*18)             // 324 halo positions
#define ACT_STRIDE 72            // == 8 mod 32 -> conflict-free frag reads
#define W_STRIDE   72
#define S_ACT_SIZE (NPOS*ACT_STRIDE)    // 23328 floats
#define S_W_SIZE   (64*W_STRIDE)        // 4608 floats
#define SMEM_BYTES ((S_ACT_SIZE + S_W_SIZE)*4)   // 111744 B

// ---------------- device scratch ----------------
__device__ float g_t1[TOTAL];
__device__ float g_t2[TOTAL];
__device__ float g_w1[9*COUT*64];   // [tap][co][ci_slot]
__device__ float g_w2[9*COUT*64];
__device__ float g_sum[2][COUT];
__device__ float g_sq[2][COUT];
__device__ float g_scale[2][COUT];
__device__ float g_bias[2][COUT];

__device__ __forceinline__ uint32_t to_tf32_bits(float x) {
    uint32_t r;
    asm("cvt.rna.tf32.f32 %0, %1;" : "=r"(r) : "f"(x));
    return r;
}
__device__ __forceinline__ uint32_t fau(float x) { return __float_as_uint(x); }

__device__ __forceinline__ void mma8(float* d, const uint32_t* a, uint32_t b0, uint32_t b1) {
    asm volatile(
        "mma.sync.aligned.m16n8k8.row.col.f32.tf32.tf32.f32 "
        "{%0,%1,%2,%3}, {%4,%5,%6,%7}, {%8,%9}, {%0,%1,%2,%3};\n"
        : "+f"(d[0]), "+f"(d[1]), "+f"(d[2]), "+f"(d[3])
        : "r"(a[0]), "r"(a[1]), "r"(a[2]), "r"(a[3]), "r"(b0), "r"(b1));
}

// within each 8-group: [0,4,1,5,2,6,3,7] -> mma k-pairs are v2-adjacent
__device__ __forceinline__ int ci_slot(int ci) {
    int grp = ci >> 3, q = ci & 3, hi = (ci >> 2) & 1;
    return grp*8 + q*2 + hi;
}

// ---------------- prep: ternarize + repack + zero stats ----------------
__global__ void prep_kernel(const float* __restrict__ w1,
                            const float* __restrict__ w2) {
    int idx = blockIdx.x * 256 + threadIdx.x;
    if (idx < COUT) {
        g_sum[0][idx] = 0.f; g_sum[1][idx] = 0.f;
        g_sq[0][idx]  = 0.f; g_sq[1][idx]  = 0.f;
    }
    if (idx < 9*COUT*64) {
        // src OIHW: idx = (co*64 + ci)*9 + t
        int co = idx / (64*9);
        int ci = (idx / 9) & 63;
        int t  = idx % 9;
        int dst = t*4096 + co*64 + ci_slot(ci);
        float a = w1[idx];
        g_w1[dst] = (fabsf(a) > 0.3f) ? (a > 0.f ? 1.f : -1.f) : 0.f;
        float b = w2[idx];
        g_w2[dst] = (fabsf(b) > 0.3f) ? (b > 0.f ? 1.f : -1.f) : 0.f;
    }
}

// ---------------- conv3x3 via 9 shifted 1x1 GEMMs, tf32 mma ----------------
// PASS 1: in=x (raw), out=g_t1.   PASS 2: in=BN1+hardtanh(g_t1), out=g_t2+x.
// Batch-norm stats of the written tensor are accumulated in the epilogue.
template<int PASS>
__global__ void __launch_bounds__(256, 2) conv_mma_kernel(const float* __restrict__ x) {
    extern __shared__ float smem[];
    float* s_act = smem;                 // [pos][ci_slot] stride 72
    float* s_w   = smem + S_ACT_SIZE;    // [co][ci_slot]  stride 72
    __shared__ float s_s[COUT], s_b[COUT];
    __shared__ float s_sum[COUT], s_sq[COUT];

    const float* in   = (PASS == 1) ? x    : g_t1;
    const float* wrep = (PASS == 1) ? g_w1 : g_w2;
    float*       out  = (PASS == 1) ? g_t1 : g_t2;

    const int tid  = threadIdx.x;
    const int lane = tid & 31;
    const int wid  = tid >> 5;
    const int wm   = wid & 1;        // 2 m-tiles of 32 co
    const int wn   = wid >> 1;       // 4 n-tiles of 64 px
    const int q    = lane & 3;
    const int nidx = lane >> 2;
    const int w0   = blockIdx.x * TPX;
    const int h0   = blockIdx.y * TPY;
    const int n    = blockIdx.z;

    if (tid < COUT) {
        s_sum[tid] = 0.f; s_sq[tid] = 0.f;
        if (PASS == 2) { s_s[tid] = g_scale[0][tid]; s_b[tid] = g_bias[0][tid]; }
    }
    __syncthreads();

    // prefetch tap-0 weights (float4 x4 per thread)
    float4 wpf[4];
#pragma unroll
    for (int k = 0; k < 4; k++)
        wpf[k] = reinterpret_cast<const float4*>(wrep)[tid + k*256];

    // stage activation tile: 64 ci x 18x18 halo, tf32-rounded.
    // t -> (a = t&3, pos = (t>>2)%324, b = t/1296), ci = a + 4b:
    // lanes split 4 ci x 8 pos -> STS 2-way, gmem 32B-sector efficient.
    for (int t = tid; t < 64*NPOS; t += 256) {
        int a   = t & 3;
        int t2  = t >> 2;
        int b   = t2 / NPOS;
        int pos = t2 - b*NPOS;
        int ci  = a + 4*b;
        int py  = pos / 18;
        int px  = pos - py*18;
        int gh = h0 + py - 1, gw = w0 + px - 1;
        float v = 0.f;
        if ((unsigned)gh < (unsigned)HH && (unsigned)gw < (unsigned)WW) {
            v = in[(n*64 + ci)*HW + gh*WW + gw];
            if (PASS == 2)
                v = fminf(fmaxf(fmaf(v, s_s[ci], s_b[ci]), -1.f), 1.f);
        }
        s_act[pos*ACT_STRIDE + ci_slot(ci)] = __uint_as_float(to_tf32_bits(v));
    }

    float acc[2][8][4];
#pragma unroll
    for (int mt = 0; mt < 2; mt++)
#pragma unroll
        for (int nt = 0; nt < 8; nt++)
#pragma unroll
            for (int r = 0; r < 4; r++) acc[mt][nt][r] = 0.f;

    for (int tap = 0; tap < 9; ++tap) {
        if (tap > 0) __syncthreads();   // prior compute done reading s_w

        // commit prefetched weights: idx4 = tid + k*256 -> co = idx4>>4, slot = (idx4&15)*4
#pragma unroll
        for (int k = 0; k < 4; k++) {
            int idx4 = tid + k*256;
            int co   = idx4 >> 4;
            int sl   = (idx4 & 15) * 4;
            *reinterpret_cast<float4*>(s_w + co*W_STRIDE + sl) = wpf[k];
        }
        if (tap < 8) {
            const float4* wsrc = reinterpret_cast<const float4*>(wrep + (tap+1)*4096);
#pragma unroll
            for (int k = 0; k < 4; k++) wpf[k] = wsrc[tid + k*256];
        }
        __syncthreads();                // s_w (and on tap 0, s_act) ready

        const int dy = tap / 3, dx = tap - dy*3;

        unsigned baddr[8];
#pragma unroll
        for (int nt = 0; nt < 8; nt++) {
            int p  = wn*64 + nt*8 + nidx;
            int py = p >> 4, px = p & 15;
            baddr[nt] = ((py + dy)*18 + (px + dx))*ACT_STRIDE + 2*q;
        }
        unsigned aaddr[2][2];
#pragma unroll
        for (int mt = 0; mt < 2; mt++) {
            int r0 = wm*32 + mt*16 + nidx;
            aaddr[mt][0] = r0*W_STRIDE + 2*q;
            aaddr[mt][1] = (r0 + 8)*W_STRIDE + 2*q;
        }

#pragma unroll
        for (int kc = 0; kc < 8; kc++) {
            const int ko = kc*8;
            uint32_t a[2][4];
#pragma unroll
            for (int mt = 0; mt < 2; mt++) {
                float2 a02 = *(const float2*)(s_w + aaddr[mt][0] + ko);
                float2 a13 = *(const float2*)(s_w + aaddr[mt][1] + ko);
                a[mt][0] = fau(a02.x); a[mt][1] = fau(a13.x);
                a[mt][2] = fau(a02.y); a[mt][3] = fau(a13.y);
            }
#pragma unroll
            for (int nt = 0; nt < 8; nt++) {
                float2 b01 = *(const float2*)(s_act + baddr[nt] + ko);
                uint32_t b0 = fau(b01.x), b1 = fau(b01.y);
#pragma unroll
                for (int mt = 0; mt < 2; mt++)
                    mma8(acc[mt][nt], a[mt], b0, b1);
            }
        }
    }

    // ---- epilogue: residual (+PASS2), store, fused BN stats ----
#pragma unroll
    for (int mt = 0; mt < 2; mt++) {
        int co_lo = wm*32 + mt*16 + nidx;
        float slo = 0.f, qlo = 0.f, shi = 0.f, qhi = 0.f;
#pragma unroll
        for (int nt = 0; nt < 8; nt++) {
            int p  = wn*64 + nt*8 + 2*q;
            int py = p >> 4, px = p & 15;
            int base = (n*64 + co_lo)*HW + (h0 + py)*WW + (w0 + px);
            float2 v0 = make_float2(acc[mt][nt][0], acc[mt][nt][1]);
            float2 v1 = make_float2(acc[mt][nt][2], acc[mt][nt][3]);
            if (PASS == 2) {
                float2 r0 = *(const float2*)(x + base);
                float2 r1 = *(const float2*)(x + base + 8*HW);
                v0.x += r0.x; v0.y += r0.y;
                v1.x += r1.x; v1.y += r1.y;
            }
            *(float2*)(out + base)        = v0;
            *(float2*)(out + base + 8*HW) = v1;
            slo += v0.x + v0.y;
            qlo += v0.x*v0.x + v0.y*v0.y;
            shi += v1.x + v1.y;
            qhi += v1.x*v1.x + v1.y*v1.y;
        }
        // reduce over the 4 q-lanes (same nidx -> same channels)
#pragma unroll
        for (int o = 1; o <= 2; o <<= 1) {
            slo += __shfl_xor_sync(0xffffffffu, slo, o);
            qlo += __shfl_xor_sync(0xffffffffu, qlo, o);
            shi += __shfl_xor_sync(0xffffffffu, shi, o);
            qhi += __shfl_xor_sync(0xffffffffu, qhi, o);
        }
        if (q == 0) {
            atomicAdd(&s_sum[co_lo],     slo);
            atomicAdd(&s_sq[co_lo],      qlo);
            atomicAdd(&s_sum[co_lo + 8], shi);
            atomicAdd(&s_sq[co_lo + 8],  qhi);
        }
    }
    __syncthreads();
    if (tid < COUT) {
        atomicAdd(&g_sum[PASS-1][tid], s_sum[tid]);
        atomicAdd(&g_sq[PASS-1][tid],  s_sq[tid]);
    }
}

// ---------------- fold BN stats ----------------
template<int PASS>
__global__ void finalize_kernel(const float* __restrict__ g,
                                const float* __restrict__ b) {
    int c = threadIdx.x;
    if (c < COUT) {
        const float inv = 1.f / (float)MCNT;
        float mean = g_sum[PASS-1][c] * inv;
        float var  = g_sq[PASS-1][c] * inv - mean*mean;
        float s    = g[c] * rsqrtf(var + 1e-5f);
        g_scale[PASS-1][c] = s;
        g_bias[PASS-1][c]  = b[c] - mean*s;
    }
}

// ---------------- final BN2 + hardtanh ----------------
__global__ void bnact_kernel(float* __restrict__ out) {
    int i = blockIdx.x * 256 + threadIdx.x;
    if (i >= TOTAL/4) return;
    int c = (i / (HW/4)) & 63;
    float s  = g_scale[1][c];
    float bb = g_bias[1][c];
    float4 v = reinterpret_cast<const float4*>(g_t2)[i];
    v.x = fminf(fmaxf(fmaf(v.x, s, bb), -1.f), 1.f);
    v.y = fminf(fmaxf(fmaf(v.y, s, bb), -1.f), 1.f);
    v.z = fminf(fmaxf(fmaf(v.z, s, bb), -1.f), 1.f);
    v.w = fminf(fmaxf(fmaf(v.w, s, bb), -1.f), 1.f);
    reinterpret_cast<float4*>(out)[i] = v;
}

// ---------------- launch ----------------
extern "C" void kernel_launch(void* const* d_in, const int* in_sizes, int n_in,
                              void* d_out, int out_size) {
    const float* x  = (const float*)d_in[0];
    const float* w1 = (const float*)d_in[1];
    const float* g1 = (const float*)d_in[2];
    const float* b1 = (const float*)d_in[3];
    const float* w2 = (const float*)d_in[4];
    const float* g2 = (const float*)d_in[5];
    const float* b2 = (const float*)d_in[6];
    float* out = (float*)d_out;

    cudaFuncSetAttribute(conv_mma_kernel<1>,
                         cudaFuncAttributeMaxDynamicSharedMemorySize, SMEM_BYTES);
    cudaFuncSetAttribute(conv_mma_kernel<2>,
                         cudaFuncAttributeMaxDynamicSharedMemorySize, SMEM_BYTES);

    prep_kernel<<<(9*COUT*64 + 255)/256, 256>>>(w1, w2);

    dim3 cgrid(WW/TPX, HH/TPY, NB);   // (7, 7, 32)
    conv_mma_kernel<1><<<cgrid, 256, SMEM_BYTES>>>(x);
    finalize_kernel<1><<<1, 64>>>(g1, b1);

    conv_mma_kernel<2><<<cgrid, 256, SMEM_BYTES>>>(x);
    finalize_kernel<2><<<1, 64>>>(g2, b2);

    bnact_kernel<<<(TOTAL/4 + 255)/256, 256>>>(out);
}

// round 5
// speedup vs baseline: 7.8153x; 1.9362x over previous
#include <cuda_runtime.h>
#include <cuda_fp16.h>
#include <math.h>
#include <stdint.h>

#define CIN   64
#define COUT  64
#define HH    112
#define WW    112
#define NB    32
#define HW    (HH*WW)            // 12544
#define TOTAL (NB*COUT*HW)       // 25690112
#define MCNT  (NB*HW)            // 401408

// conv tiling: block = 64 co x 256 px (16x16), 8 warps m32xn64, fp16 mma k16
#define TPX 16
#define TPY 16
#define NPOS (18*18)             // 324 halo positions
#define ASTR 80                  // halves per pos row (== 8 words mod 32: conflict-free)
#define WSTR 80                  // halves per co row
#define S_ACT_HALVES (NPOS*ASTR)          // 25920
#define S_W_HALVES   (64*WSTR)            // 5120 per buffer (x2 double-buffered)
#define SMEM_BYTES ((S_ACT_HALVES + 2*S_W_HALVES)*2)   // 72320 B

// ---------------- device scratch ----------------
__device__ float  g_t1[TOTAL];
__device__ float  g_t2[TOTAL];
__device__ __half g_w1[9*64*64];   // [tap][co][k_slot]
__device__ __half g_w2[9*64*64];
__device__ float  g_sum[2][COUT];
__device__ float  g_sq[2][COUT];
__device__ float  g_scale[2][COUT];
__device__ float  g_bias[2][COUT];

// k-permutation within a 16-chunk: slot order = [2q,2q+1,2q+8,2q+9] adjacent
// f(k) = 4*(k>>1 & 3) + (k&1) + 2*(k>>3)
__device__ __forceinline__ int kperm(int k) {
    return ((k & 6) << 1) | (k & 1) | ((k & 8) >> 2);
}
__device__ __forceinline__ int ci_slot(int ci) {
    return (ci & 48) | kperm(ci & 15);
}

__device__ __forceinline__ void mma16(float* d, const uint32_t* a, uint32_t b0, uint32_t b1) {
    asm volatile(
        "mma.sync.aligned.m16n8k16.row.col.f32.f16.f16.f32 "
        "{%0,%1,%2,%3}, {%4,%5,%6,%7}, {%8,%9}, {%0,%1,%2,%3};\n"
        : "+f"(d[0]), "+f"(d[1]), "+f"(d[2]), "+f"(d[3])
        : "r"(a[0]), "r"(a[1]), "r"(a[2]), "r"(a[3]), "r"(b0), "r"(b1));
}

// ---------------- prep: ternarize + repack(half) + zero stats ----------------
__global__ void prep_kernel(const float* __restrict__ w1,
                            const float* __restrict__ w2) {
    int idx = blockIdx.x * 256 + threadIdx.x;
    if (idx < COUT) {
        g_sum[0][idx] = 0.f; g_sum[1][idx] = 0.f;
        g_sq[0][idx]  = 0.f; g_sq[1][idx]  = 0.f;
    }
    if (idx < 9*64*64) {
        // src OIHW: idx = (co*64 + ci)*9 + t
        int co = idx / (64*9);
        int ci = (idx / 9) & 63;
        int t  = idx % 9;
        int dst = t*4096 + co*64 + ci_slot(ci);
        float a = w1[idx];
        g_w1[dst] = __float2half((fabsf(a) > 0.3f) ? (a > 0.f ? 1.f : -1.f) : 0.f);
        float b = w2[idx];
        g_w2[dst] = __float2half((fabsf(b) > 0.3f) ? (b > 0.f ? 1.f : -1.f) : 0.f);
    }
}

// ---------------- conv3x3 via 9 shifted 1x1 GEMMs, fp16 mma, fp32 accum ----
// PASS 1: in=x, out=g_t1.  PASS 2: in=BN1+hardtanh(g_t1), out=g_t2 + x.
// BN stats of the written tensor accumulated in the epilogue.
template<int PASS>
__global__ void __launch_bounds__(256, 2) conv_mma_kernel(const float* __restrict__ x) {
    extern __shared__ __half smem_h[];
    __half* s_act = smem_h;                       // [pos][k_slot] stride 80
    __half* s_wb  = smem_h + S_ACT_HALVES;        // 2 weight buffers
    __shared__ float s_s[COUT], s_b[COUT];
    __shared__ float s_sum[COUT], s_sq[COUT];

    const float*  in   = (PASS == 1) ? x    : g_t1;
    const __half* wrep = (PASS == 1) ? g_w1 : g_w2;
    float*        out  = (PASS == 1) ? g_t1 : g_t2;

    const int tid  = threadIdx.x;
    const int lane = tid & 31;
    const int wid  = tid >> 5;
    const int wm   = wid & 1;        // 2 m-tiles of 32 co
    const int wn   = wid >> 1;       // 4 n-tiles of 64 px
    const int q    = lane & 3;
    const int nidx = lane >> 2;
    const int w0   = blockIdx.x * TPX;
    const int h0   = blockIdx.y * TPY;
    const int n    = blockIdx.z;

    if (tid < COUT) {
        s_sum[tid] = 0.f; s_sq[tid] = 0.f;
        if (PASS == 2) { s_s[tid] = g_scale[0][tid]; s_b[tid] = g_bias[0][tid]; }
    }
    __syncthreads();

    // prefetch tap-0 weights (2 x float4 = 16 halves / thread)
    float4 wpf[2];
#pragma unroll
    for (int k = 0; k < 2; k++)
        wpf[k] = reinterpret_cast<const float4*>(wrep)[tid + k*256];

    // ---- stage activation tile: 64 ci x 18x18 halo, fp16 ----
    // lanes: 4 pos-workers x 8 ci-pair-workers -> conflict-free half2 STS
    {
        const int posw = (tid & 3) | ((tid >> 5) << 2);   // 0..31
        const int cpw  = (tid >> 2) & 7;                  // 0..7
        const int kp   = kperm(2*cpw);                    // slot base for this worker
        const int ci0  = 2*cpw;
        for (int pos = posw; pos < NPOS; pos += 32) {
            int py = pos / 18;
            int px = pos - py*18;
            int gh = h0 + py - 1, gw = w0 + px - 1;
            bool valid = ((unsigned)gh < (unsigned)HH) && ((unsigned)gw < (unsigned)WW);
            const float* p0 = in + (n*64)*HW + gh*WW + gw;
            int word = pos*ASTR;
#pragma unroll
            for (int j = 0; j < 4; j++) {
                int ci = ci0 + 16*j;
                float v0 = 0.f, v1 = 0.f;
                if (valid) {
                    const float* p = p0 + ci*HW;
                    v0 = p[0];
                    v1 = p[HW];
                    if (PASS == 2) {
                        v0 = fminf(fmaxf(fmaf(v0, s_s[ci],   s_b[ci]),   -1.f), 1.f);
                        v1 = fminf(fmaxf(fmaf(v1, s_s[ci+1], s_b[ci+1]), -1.f), 1.f);
                    }
                }
                *reinterpret_cast<__half2*>(s_act + word + 16*j + kp) =
                    __floats2half2_rn(v0, v1);
            }
        }
    }

    float acc[2][8][4];
#pragma unroll
    for (int mt = 0; mt < 2; mt++)
#pragma unroll
        for (int nt = 0; nt < 8; nt++)
#pragma unroll
            for (int r = 0; r < 4; r++) acc[mt][nt][r] = 0.f;

    for (int tap = 0; tap < 9; ++tap) {
        __half* s_w = s_wb + (tap & 1)*S_W_HALVES;
        // commit prefetched weights: v = tid + k*256 -> co = v>>3, 8-half group = (v&7)*8
#pragma unroll
        for (int k = 0; k < 2; k++) {
            int v = tid + k*256;
            *reinterpret_cast<float4*>(s_w + (v >> 3)*WSTR + (v & 7)*8) = wpf[k];
        }
        if (tap < 8) {
            const float4* wsrc = reinterpret_cast<const float4*>(wrep + (tap+1)*4096);
#pragma unroll
            for (int k = 0; k < 2; k++) wpf[k] = wsrc[tid + k*256];
        }
        __syncthreads();   // weights (and on tap 0, act tile) ready

        const int dy = tap / 3, dx = tap - dy*3;

        unsigned baddr[8];
#pragma unroll
        for (int nt = 0; nt < 8; nt++) {
            int p  = wn*64 + nt*8 + nidx;
            int py = p >> 4, px = p & 15;
            baddr[nt] = ((py + dy)*18 + (px + dx))*ASTR + 4*q;
        }
        unsigned aaddr[2][2];
#pragma unroll
        for (int mt = 0; mt < 2; mt++) {
            int r0 = wm*32 + mt*16 + nidx;
            aaddr[mt][0] = r0*WSTR + 4*q;
            aaddr[mt][1] = (r0 + 8)*WSTR + 4*q;
        }

#pragma unroll
        for (int ch = 0; ch < 4; ch++) {
            const int ko = ch*16;
            uint32_t a[2][4];
#pragma unroll
            for (int mt = 0; mt < 2; mt++) {
                uint2 lo = *reinterpret_cast<const uint2*>(s_w + aaddr[mt][0] + ko);
                uint2 hi = *reinterpret_cast<const uint2*>(s_w + aaddr[mt][1] + ko);
                a[mt][0] = lo.x; a[mt][1] = hi.x; a[mt][2] = lo.y; a[mt][3] = hi.y;
            }
#pragma unroll
            for (int nt = 0; nt < 8; nt++) {
                uint2 b = *reinterpret_cast<const uint2*>(s_act + baddr[nt] + ko);
#pragma unroll
                for (int mt = 0; mt < 2; mt++)
                    mma16(acc[mt][nt], a[mt], b.x, b.y);
            }
        }
    }

    // ---- epilogue: residual (+PASS2), store, fused BN stats ----
#pragma unroll
    for (int mt = 0; mt < 2; mt++) {
        int co_lo = wm*32 + mt*16 + nidx;
        float slo = 0.f, qlo = 0.f, shi = 0.f, qhi = 0.f;
#pragma unroll
        for (int nt = 0; nt < 8; nt++) {
            int p  = wn*64 + nt*8 + 2*q;
            int py = p >> 4, px = p & 15;
            int base = (n*64 + co_lo)*HW + (h0 + py)*WW + (w0 + px);
            float2 v0 = make_float2(acc[mt][nt][0], acc[mt][nt][1]);
            float2 v1 = make_float2(acc[mt][nt][2], acc[mt][nt][3]);
            if (PASS == 2) {
                float2 r0 = *(const float2*)(x + base);
                float2 r1 = *(const float2*)(x + base + 8*HW);
                v0.x += r0.x; v0.y += r0.y;
                v1.x += r1.x; v1.y += r1.y;
            }
            *(float2*)(out + base)        = v0;
            *(float2*)(out + base + 8*HW) = v1;
            slo += v0.x + v0.y;
            qlo += v0.x*v0.x + v0.y*v0.y;
            shi += v1.x + v1.y;
            qhi += v1.x*v1.x + v1.y*v1.y;
        }
#pragma unroll
        for (int o = 1; o <= 2; o <<= 1) {
            slo += __shfl_xor_sync(0xffffffffu, slo, o);
            qlo += __shfl_xor_sync(0xffffffffu, qlo, o);
            shi += __shfl_xor_sync(0xffffffffu, shi, o);
            qhi += __shfl_xor_sync(0xffffffffu, qhi, o);
        }
        if (q == 0) {
            atomicAdd(&s_sum[co_lo],     slo);
            atomicAdd(&s_sq[co_lo],      qlo);
            atomicAdd(&s_sum[co_lo + 8], shi);
            atomicAdd(&s_sq[co_lo + 8],  qhi);
        }
    }
    __syncthreads();
    if (tid < COUT) {
        atomicAdd(&g_sum[PASS-1][tid], s_sum[tid]);
        atomicAdd(&g_sq[PASS-1][tid],  s_sq[tid]);
    }
}

// ---------------- fold BN stats ----------------
template<int PASS>
__global__ void finalize_kernel(const float* __restrict__ g,
                                const float* __restrict__ b) {
    int c = threadIdx.x;
    if (c < COUT) {
        const float inv = 1.f / (float)MCNT;
        float mean = g_sum[PASS-1][c] * inv;
        float var  = g_sq[PASS-1][c] * inv - mean*mean;
        float s    = g[c] * rsqrtf(var + 1e-5f);
        g_scale[PASS-1][c] = s;
        g_bias[PASS-1][c]  = b[c] - mean*s;
    }
}

// ---------------- final BN2 + hardtanh ----------------
__global__ void bnact_kernel(float* __restrict__ out) {
    int i = blockIdx.x * 256 + threadIdx.x;
    if (i >= TOTAL/4) return;
    int c = (i / (HW/4)) & 63;
    float s  = g_scale[1][c];
    float bb = g_bias[1][c];
    float4 v = reinterpret_cast<const float4*>(g_t2)[i];
    v.x = fminf(fmaxf(fmaf(v.x, s, bb), -1.f), 1.f);
    v.y = fminf(fmaxf(fmaf(v.y, s, bb), -1.f), 1.f);
    v.z = fminf(fmaxf(fmaf(v.z, s, bb), -1.f), 1.f);
    v.w = fminf(fmaxf(fmaf(v.w, s, bb), -1.f), 1.f);
    reinterpret_cast<float4*>(out)[i] = v;
}

// ---------------- launch ----------------
extern "C" void kernel_launch(void* const* d_in, const int* in_sizes, int n_in,
                              void* d_out, int out_size) {
    const float* x  = (const float*)d_in[0];
    const float* w1 = (const float*)d_in[1];
    const float* g1 = (const float*)d_in[2];
    const float* b1 = (const float*)d_in[3];
    const float* w2 = (const float*)d_in[4];
    const float* g2 = (const float*)d_in[5];
    const float* b2 = (const float*)d_in[6];
    float* out = (float*)d_out;

    cudaFuncSetAttribute(conv_mma_kernel<1>,
                         cudaFuncAttributeMaxDynamicSharedMemorySize, SMEM_BYTES);
    cudaFuncSetAttribute(conv_mma_kernel<2>,
                         cudaFuncAttributeMaxDynamicSharedMemorySize, SMEM_BYTES);

    prep_kernel<<<(9*64*64 + 255)/256, 256>>>(w1, w2);

    dim3 cgrid(WW/TPX, HH/TPY, NB);   // (7, 7, 32)
    conv_mma_kernel<1><<<cgrid, 256, SMEM_BYTES>>>(x);
    finalize_kernel<1><<<1, 64>>>(g1, b1);

    conv_mma_kernel<2><<<cgrid, 256, SMEM_BYTES>>>(x);
    finalize_kernel<2><<<1, 64>>>(g2, b2);

    bnact_kernel<<<(TOTAL/4 + 255)/256, 256>>>(out);
}

// round 6
// speedup vs baseline: 9.3298x; 1.1938x over previous
#include <cuda_runtime.h>
#include <cuda_fp16.h>
#include <math.h>
#include <stdint.h>

#define CIN   64
#define COUT  64
#define HH    112
#define WW    112
#define NB    32
#define HW    (HH*WW)            // 12544
#define TOTAL (NB*COUT*HW)       // 25690112
#define MCNT  (NB*HW)            // 401408

// conv tiling: block = 64 co x 256 px (16x16), 8 warps m32xn64, fp16 mma k16
#define TPX 16
#define TPY 16
#define NPOS (18*18)             // 324 halo positions
#define ASTR 72                  // halves per pos row: 36 words, 36*i mod 32 distinct -> LDSM conflict-free
#define WSTR 72
#define S_ACT_HALVES (NPOS*ASTR)          // 23328
#define S_W_HALVES   (64*WSTR)            // 4608 per buffer (x2)
#define SMEM_BYTES ((S_ACT_HALVES + 2*S_W_HALVES)*2)   // 65088 B

// ---------------- device scratch ----------------
__device__ float  g_t1[TOTAL];
__device__ float  g_t2[TOTAL];
__device__ __half g_w1[9*64*64];   // [tap][co][ci] plain
__device__ __half g_w2[9*64*64];
__device__ float  g_sum[2][COUT];
__device__ float  g_sq[2][COUT];
__device__ float  g_scale[2][COUT];
__device__ float  g_bias[2][COUT];

__device__ __forceinline__ void mma16(float* d, const uint32_t* a, uint32_t b0, uint32_t b1) {
    asm volatile(
        "mma.sync.aligned.m16n8k16.row.col.f32.f16.f16.f32 "
        "{%0,%1,%2,%3}, {%4,%5,%6,%7}, {%8,%9}, {%0,%1,%2,%3};\n"
        : "+f"(d[0]), "+f"(d[1]), "+f"(d[2]), "+f"(d[3])
        : "r"(a[0]), "r"(a[1]), "r"(a[2]), "r"(a[3]), "r"(b0), "r"(b1));
}
__device__ __forceinline__ void ldsm4(uint32_t& r0, uint32_t& r1, uint32_t& r2, uint32_t& r3,
                                      uint32_t addr) {
    asm volatile("ldmatrix.sync.aligned.m8n8.x4.shared.b16 {%0,%1,%2,%3}, [%4];"
        : "=r"(r0), "=r"(r1), "=r"(r2), "=r"(r3) : "r"(addr));
}

// ---------------- prep: ternarize + repack(half) + zero stats ----------------
__global__ void prep_kernel(const float* __restrict__ w1,
                            const float* __restrict__ w2) {
    int idx = blockIdx.x * 256 + threadIdx.x;
    if (idx < COUT) {
        g_sum[0][idx] = 0.f; g_sum[1][idx] = 0.f;
        g_sq[0][idx]  = 0.f; g_sq[1][idx]  = 0.f;
    }
    if (idx < 9*64*64) {
        // src OIHW: idx = (co*64 + ci)*9 + t
        int co = idx / (64*9);
        int ci = (idx / 9) & 63;
        int t  = idx % 9;
        int dst = t*4096 + co*64 + ci;
        float a = w1[idx];
        g_w1[dst] = __float2half((fabsf(a) > 0.3f) ? (a > 0.f ? 1.f : -1.f) : 0.f);
        float b = w2[idx];
        g_w2[dst] = __float2half((fabsf(b) > 0.3f) ? (b > 0.f ? 1.f : -1.f) : 0.f);
    }
}

// ---------------- conv3x3 via 9 shifted 1x1 GEMMs, fp16 mma + ldmatrix ----
// PASS 1: in=x, out=g_t1.  PASS 2: in=BN1+hardtanh(g_t1), out=g_t2 + x.
// BN stats of the written tensor accumulated in the epilogue.
template<int PASS>
__global__ void __launch_bounds__(256, 2) conv_mma_kernel(const float* __restrict__ x) {
    extern __shared__ __half smem_h[];
    __half* s_act = smem_h;                       // [pos][ci] stride 72
    __half* s_wb  = smem_h + S_ACT_HALVES;        // 2 weight buffers [co][ci] stride 72
    __shared__ float s_s[COUT], s_b[COUT];
    __shared__ float s_sum[COUT], s_sq[COUT];

    const float*  in   = (PASS == 1) ? x    : g_t1;
    const __half* wrep = (PASS == 1) ? g_w1 : g_w2;
    float*        out  = (PASS == 1) ? g_t1 : g_t2;

    const int tid  = threadIdx.x;
    const int lane = tid & 31;
    const int wid  = tid >> 5;
    const int wm   = wid & 1;        // 2 m-tiles of 32 co
    const int wn   = wid >> 1;       // 4 n-tiles of 64 px
    const int q    = lane & 3;
    const int nidx = lane >> 2;
    const int w0   = blockIdx.x * TPX;
    const int h0   = blockIdx.y * TPY;
    const int n    = blockIdx.z;

    if (tid < COUT) {
        s_sum[tid] = 0.f; s_sq[tid] = 0.f;
        if (PASS == 2) { s_s[tid] = g_scale[0][tid]; s_b[tid] = g_bias[0][tid]; }
    }
    __syncthreads();

    // prefetch tap-0 weights (2 x float4 = 16 halves / thread)
    float4 wpf[2];
#pragma unroll
    for (int k = 0; k < 2; k++)
        wpf[k] = reinterpret_cast<const float4*>(wrep)[tid + k*256];

    // ---- stage activation tile: 64 ci x 18x18 halo, fp16, plain [pos][ci] ----
    {
        const int posw = (tid & 3) | ((tid >> 5) << 2);   // 0..31
        const int cpw  = (tid >> 2) & 7;                  // 0..7
        const int ci0  = 2*cpw;
        for (int pos = posw; pos < NPOS; pos += 32) {
            int py = pos / 18;
            int px = pos - py*18;
            int gh = h0 + py - 1, gw = w0 + px - 1;
            bool valid = ((unsigned)gh < (unsigned)HH) && ((unsigned)gw < (unsigned)WW);
            const float* p0 = in + (n*64)*HW + gh*WW + gw;
            int word = pos*ASTR;
#pragma unroll
            for (int j = 0; j < 4; j++) {
                int ci = ci0 + 16*j;
                float v0 = 0.f, v1 = 0.f;
                if (valid) {
                    const float* p = p0 + ci*HW;
                    v0 = p[0];
                    v1 = p[HW];
                    if (PASS == 2) {
                        v0 = fminf(fmaxf(fmaf(v0, s_s[ci],   s_b[ci]),   -1.f), 1.f);
                        v1 = fminf(fmaxf(fmaf(v1, s_s[ci+1], s_b[ci+1]), -1.f), 1.f);
                    }
                }
                *reinterpret_cast<__half2*>(s_act + word + ci) = __floats2half2_rn(v0, v1);
            }
        }
    }

    float acc[2][8][4];
#pragma unroll
    for (int mt = 0; mt < 2; mt++)
#pragma unroll
        for (int nt = 0; nt < 8; nt++)
#pragma unroll
            for (int r = 0; r < 4; r++) acc[mt][nt][r] = 0.f;

    // ---- per-lane LDSM base addresses (byte offsets in shared space) ----
    const uint32_t sw_b  = (uint32_t)__cvta_generic_to_shared(s_wb);
    const uint32_t sa_b  = (uint32_t)__cvta_generic_to_shared(s_act);
    // A: lanes 0-7 rows m0-7 @k0 | 8-15 rows m8-15 @k0 | 16-23 m0-7 @k8 | 24-31 m8-15 @k8
    const uint32_t aA = sw_b + (((wm*32 + (lane & 15))*WSTR) + (lane >> 4)*8) * 2;
    // B: lanes 0-7 n0-7 @k0 | 8-15 n0-7 @k8 | 16-23 n8-15 @k0 | 24-31 n8-15 @k8 (per pair)
    const int px_l  = ((lane >> 4) & 1)*8 + (lane & 7);
    const int kof_l = ((lane >> 3) & 1)*8;
    const uint32_t bB = sa_b + (((wn*4)*18 + px_l)*ASTR + kof_l) * 2;

#pragma unroll
    for (int tap = 0; tap < 9; ++tap) {
        __half* s_w = s_wb + (tap & 1)*S_W_HALVES;
        const uint32_t wbuf = (tap & 1) * (S_W_HALVES*2);
#pragma unroll
        for (int k = 0; k < 2; k++) {
            int v = tid + k*256;
            *reinterpret_cast<float4*>(s_w + (v >> 3)*WSTR + (v & 7)*8) = wpf[k];
        }
        if (tap < 8) {
            const float4* wsrc = reinterpret_cast<const float4*>(wrep + (tap+1)*4096);
#pragma unroll
            for (int k = 0; k < 2; k++) wpf[k] = wsrc[tid + k*256];
        }
        __syncthreads();   // buffer (tap&1) ready; prior reads of it finished a tap ago

        const int dy = tap / 3, dx = tap - dy*3;
        const uint32_t tapoff = (uint32_t)((dy*18 + dx)*ASTR*2);

#pragma unroll
        for (int ch = 0; ch < 4; ch++) {
            const uint32_t ko = ch*32;           // 16 halves per chunk
            uint32_t a[2][4];
            ldsm4(a[0][0], a[0][1], a[0][2], a[0][3], aA + wbuf + ko);
            ldsm4(a[1][0], a[1][1], a[1][2], a[1][3], aA + wbuf + ko + 16*WSTR*2);
#pragma unroll
            for (int pr = 0; pr < 4; pr++) {
                uint32_t b0, b1, b2, b3;
                ldsm4(b0, b1, b2, b3, bB + tapoff + (uint32_t)(pr*18*ASTR*2) + ko);
                mma16(acc[0][2*pr],   a[0], b0, b1);
                mma16(acc[1][2*pr],   a[1], b0, b1);
                mma16(acc[0][2*pr+1], a[0], b2, b3);
                mma16(acc[1][2*pr+1], a[1], b2, b3);
            }
        }
    }

    // ---- epilogue: residual (+PASS2), store, fused BN stats ----
#pragma unroll
    for (int mt = 0; mt < 2; mt++) {
        int co_lo = wm*32 + mt*16 + nidx;
        float slo = 0.f, qlo = 0.f, shi = 0.f, qhi = 0.f;
#pragma unroll
        for (int nt = 0; nt < 8; nt++) {
            int p  = wn*64 + nt*8 + 2*q;
            int py = p >> 4, px = p & 15;
            int base = (n*64 + co_lo)*HW + (h0 + py)*WW + (w0 + px);
            float2 v0 = make_float2(acc[mt][nt][0], acc[mt][nt][1]);
            float2 v1 = make_float2(acc[mt][nt][2], acc[mt][nt][3]);
            if (PASS == 2) {
                float2 r0 = *(const float2*)(x + base);
                float2 r1 = *(const float2*)(x + base + 8*HW);
                v0.x += r0.x; v0.y += r0.y;
                v1.x += r1.x; v1.y += r1.y;
            }
            *(float2*)(out + base)        = v0;
            *(float2*)(out + base + 8*HW) = v1;
            slo += v0.x + v0.y;
            qlo += v0.x*v0.x + v0.y*v0.y;
            shi += v1.x + v1.y;
            qhi += v1.x*v1.x + v1.y*v1.y;
        }
#pragma unroll
        for (int o = 1; o <= 2; o <<= 1) {
            slo += __shfl_xor_sync(0xffffffffu, slo, o);
            qlo += __shfl_xor_sync(0xffffffffu, qlo, o);
            shi += __shfl_xor_sync(0xffffffffu, shi, o);
            qhi += __shfl_xor_sync(0xffffffffu, qhi, o);
        }
        if (q == 0) {
            atomicAdd(&s_sum[co_lo],     slo);
            atomicAdd(&s_sq[co_lo],      qlo);
            atomicAdd(&s_sum[co_lo + 8], shi);
            atomicAdd(&s_sq[co_lo + 8],  qhi);
        }
    }
    __syncthreads();
    if (tid < COUT) {
        atomicAdd(&g_sum[PASS-1][tid], s_sum[tid]);
        atomicAdd(&g_sq[PASS-1][tid],  s_sq[tid]);
    }
}

// ---------------- fold BN stats ----------------
template<int PASS>
__global__ void finalize_kernel(const float* __restrict__ g,
                                const float* __restrict__ b) {
    int c = threadIdx.x;
    if (c < COUT) {
        const float inv = 1.f / (float)MCNT;
        float mean = g_sum[PASS-1][c] * inv;
        float var  = g_sq[PASS-1][c] * inv - mean*mean;
        float s    = g[c] * rsqrtf(var + 1e-5f);
        g_scale[PASS-1][c] = s;
        g_bias[PASS-1][c]  = b[c] - mean*s;
    }
}

// ---------------- final BN2 + hardtanh ----------------
__global__ void bnact_kernel(float* __restrict__ out) {
    int i = blockIdx.x * 256 + threadIdx.x;
    if (i >= TOTAL/4) return;
    int c = (i / (HW/4)) & 63;
    float s  = g_scale[1][c];
    float bb = g_bias[1][c];
    float4 v = reinterpret_cast<const float4*>(g_t2)[i];
    v.x = fminf(fmaxf(fmaf(v.x, s, bb), -1.f), 1.f);
    v.y = fminf(fmaxf(fmaf(v.y, s, bb), -1.f), 1.f);
    v.z = fminf(fmaxf(fmaf(v.z, s, bb), -1.f), 1.f);
    v.w = fminf(fmaxf(fmaf(v.w, s, bb), -1.f), 1.f);
    reinterpret_cast<float4*>(out)[i] = v;
}

// ---------------- launch ----------------
extern "C" void kernel_launch(void* const* d_in, const int* in_sizes, int n_in,
                              void* d_out, int out_size) {
    const float* x  = (const float*)d_in[0];
    const float* w1 = (const float*)d_in[1];
    const float* g1 = (const float*)d_in[2];
    const float* b1 = (const float*)d_in[3];
    const float* w2 = (const float*)d_in[4];
    const float* g2 = (const float*)d_in[5];
    const float* b2 = (const float*)d_in[6];
    float* out = (float*)d_out;

    cudaFuncSetAttribute(conv_mma_kernel<1>,
                         cudaFuncAttributeMaxDynamicSharedMemorySize, SMEM_BYTES);
    cudaFuncSetAttribute(conv_mma_kernel<2>,
                         cudaFuncAttributeMaxDynamicSharedMemorySize, SMEM_BYTES);

    prep_kernel<<<(9*64*64 + 255)/256, 256>>>(w1, w2);

    dim3 cgrid(WW/TPX, HH/TPY, NB);   // (7, 7, 32)
    conv_mma_kernel<1><<<cgrid, 256, SMEM_BYTES>>>(x);
    finalize_kernel<1><<<1, 64>>>(g1, b1);

    conv_mma_kernel<2><<<cgrid, 256, SMEM_BYTES>>>(x);
    finalize_kernel<2><<<1, 64>>>(g2, b2);

    bnact_kernel<<<(TOTAL/4 + 255)/256, 256>>>(out);
}